// round 15
// baseline (speedup 1.0000x reference)
#include <cuda_runtime.h>
#include <cuda_fp16.h>
#include <stdint.h>
#include <math.h>

#define B_  64
#define N_  1024
#define D_  512
#define K_  64
#define EPS_ 1e-12f

// ---------------- scratch ----------------
__device__ __half g_aT[(size_t)B_ * K_ * N_];            // a^T fp16 [b][k][n]
__device__ float g_asum_part[B_ * 8 * K_];
__device__ float g_S_part[B_ * 4 * K_];
__device__ unsigned int g_ctr[B_], g_done[B_];           // gemm2 norm barrier (self-clean)

// ---------------- helpers ----------------
__device__ __forceinline__ uint32_t smem_u32(const void* p) {
    uint32_t a;
    asm("{ .reg .u64 t; cvta.to.shared.u64 t, %1; cvt.u32.u64 %0, t; }" : "=r"(a) : "l"(p));
    return a;
}
__device__ __forceinline__ uint32_t sw128(uint32_t off) { return off ^ ((off >> 3) & 0x70); }
__device__ __forceinline__ uint32_t sw256(uint32_t off) { return off ^ (((off >> 8) & 7) << 4); }

__device__ __forceinline__ void ldsm_x4(uint32_t* r, uint32_t a) {
    asm volatile("ldmatrix.sync.aligned.m8n8.x4.shared.b16 {%0,%1,%2,%3}, [%4];"
        : "=r"(r[0]), "=r"(r[1]), "=r"(r[2]), "=r"(r[3]) : "r"(a));
}
__device__ __forceinline__ void ldsm_x4t(uint32_t* r, uint32_t a) {
    asm volatile("ldmatrix.sync.aligned.m8n8.x4.trans.shared.b16 {%0,%1,%2,%3}, [%4];"
        : "=r"(r[0]), "=r"(r[1]), "=r"(r[2]), "=r"(r[3]) : "r"(a));
}
__device__ __forceinline__ void mma16816(float* c, const uint32_t* a, uint32_t b0, uint32_t b1) {
    asm volatile("mma.sync.aligned.m16n8k16.row.col.f32.f16.f16.f32 "
        "{%0,%1,%2,%3}, {%4,%5,%6,%7}, {%8,%9}, {%0,%1,%2,%3};"
        : "+f"(c[0]), "+f"(c[1]), "+f"(c[2]), "+f"(c[3])
        : "r"(a[0]), "r"(a[1]), "r"(a[2]), "r"(a[3]), "r"(b0), "r"(b1));
}
__device__ __forceinline__ void sts64(uint32_t addr, uint32_t a, uint32_t b) {
    asm volatile("st.shared.v2.b32 [%0], {%1,%2};" :: "r"(addr), "r"(a), "r"(b) : "memory");
}
__device__ __forceinline__ void sts128(uint32_t addr, uint4 v) {
    asm volatile("st.shared.v4.b32 [%0], {%1,%2,%3,%4};"
        :: "r"(addr), "r"(v.x), "r"(v.y), "r"(v.z), "r"(v.w) : "memory");
}
__device__ __forceinline__ uint32_t h2(float a, float b) {
    __half2 h = __floats2half2_rn(a, b);
    return *(uint32_t*)&h;
}

// ---------------- kernel 1: s = x@w + softmax -> aT (w fp32 direct, trans-B) ----
__global__ __launch_bounds__(256) void gemm1_kernel(const float* __restrict__ x,
                                                    const float* __restrict__ w) {
    __shared__ __align__(1024) char smem[49152];
    const uint32_t S0 = smem_u32(smem);
    float* stage = (float*)smem;                   // overlay post-loop

    const int t = threadIdx.x, wid = t >> 5, l = t & 31;
    const int bIdx = blockIdx.x >> 3, tile = blockIdx.x & 7;
    const float* xb = x + ((size_t)bIdx * N_ + (size_t)tile * 128) * D_;

    float acc[8][4];
#pragma unroll
    for (int f = 0; f < 8; f++)
#pragma unroll
        for (int j = 0; j < 4; j++) acc[f][j] = 0.f;

    const int rA  = (l & 15);
    const int cA8 = (l >> 4) << 3;
    const int rB2 = (l & 7) + (((l >> 3) & 1) << 3);
    const int cB2 = ((l >> 4) & 1) << 3;

    float4 rx[8];
    float4 rw[4];

    auto ldg_chunk = [&](int c) {
        const int d0 = c * 64;
#pragma unroll
        for (int i = 0; i < 8; i++) {
            int e = t + i * 256, r = e >> 4, f4 = e & 15;
            rx[i] = *(const float4*)(xb + (size_t)r * D_ + d0 + f4 * 4);
        }
#pragma unroll
        for (int i = 0; i < 4; i++) {
            int e = t + i * 256, r = e >> 4, k4 = e & 15;
            rw[i] = *(const float4*)(w + (size_t)(d0 + r) * K_ + k4 * 4);
        }
    };
    auto sts_chunk = [&](int buf) {
        const uint32_t XH = S0 + buf * 24576, WD = XH + 16384;
#pragma unroll
        for (int i = 0; i < 8; i++) {
            int e = t + i * 256, r = e >> 4, f4 = e & 15;
            sts64(XH + sw128((uint32_t)(r * 128 + f4 * 8)),
                  h2(rx[i].x, rx[i].y), h2(rx[i].z, rx[i].w));
        }
#pragma unroll
        for (int i = 0; i < 4; i++) {
            int e = t + i * 256, r = e >> 4, k4 = e & 15;
            sts64(WD + sw128((uint32_t)(r * 128 + k4 * 8)),
                  h2(rw[i].x, rw[i].y), h2(rw[i].z, rw[i].w));
        }
    };

    ldg_chunk(0);
    sts_chunk(0);
    __syncthreads();

#pragma unroll
    for (int c = 0; c < 8; c++) {
        if (c < 7) ldg_chunk(c + 1);
        const uint32_t XH = S0 + (c & 1) * 24576, WD = XH + 16384;
#pragma unroll
        for (int ks = 0; ks < 4; ks++) {
            const int k0 = ks * 16;
            uint32_t ah[4];
            ldsm_x4(ah, XH + sw128((uint32_t)((16 * wid + rA) * 128 + (k0 + cA8) * 2)));
#pragma unroll
            for (int fp = 0; fp < 4; fp++) {
                uint32_t bh[4];
                ldsm_x4t(bh, WD + sw128((uint32_t)((k0 + rB2) * 128 + (fp * 16 + cB2) * 2)));
                mma16816(acc[2*fp],   ah, bh[0], bh[1]);
                mma16816(acc[2*fp+1], ah, bh[2], bh[3]);
            }
        }
        if (c < 7) {
            sts_chunk((c + 1) & 1);
            __syncthreads();
        }
    }
    __syncthreads();

    // softmax (rows r0 = 16*wid + l/4 and r0+8)
    const int q = l >> 2, qq = l & 3;
    const int r0 = 16 * wid + q;
    float m0 = -1e30f, m1 = -1e30f;
#pragma unroll
    for (int f = 0; f < 8; f++) {
        m0 = fmaxf(m0, fmaxf(acc[f][0], acc[f][1]));
        m1 = fmaxf(m1, fmaxf(acc[f][2], acc[f][3]));
    }
    m0 = fmaxf(m0, __shfl_xor_sync(~0u, m0, 1));
    m0 = fmaxf(m0, __shfl_xor_sync(~0u, m0, 2));
    m1 = fmaxf(m1, __shfl_xor_sync(~0u, m1, 1));
    m1 = fmaxf(m1, __shfl_xor_sync(~0u, m1, 2));
    float s0 = 0.f, s1 = 0.f;
#pragma unroll
    for (int f = 0; f < 8; f++) {
        acc[f][0] = __expf(acc[f][0] - m0);
        acc[f][1] = __expf(acc[f][1] - m0);
        acc[f][2] = __expf(acc[f][2] - m1);
        acc[f][3] = __expf(acc[f][3] - m1);
        s0 += acc[f][0] + acc[f][1];
        s1 += acc[f][2] + acc[f][3];
    }
    s0 += __shfl_xor_sync(~0u, s0, 1); s0 += __shfl_xor_sync(~0u, s0, 2);
    s1 += __shfl_xor_sync(~0u, s1, 1); s1 += __shfl_xor_sync(~0u, s1, 2);
    const float i0 = 1.0f / s0, i1 = 1.0f / s1;
#pragma unroll
    for (int f = 0; f < 8; f++) {
        *(float2*)&stage[r0 * 66 + 8 * f + 2 * qq]       = make_float2(acc[f][0] * i0, acc[f][1] * i0);
        *(float2*)&stage[(r0 + 8) * 66 + 8 * f + 2 * qq] = make_float2(acc[f][2] * i1, acc[f][3] * i1);
    }
    __syncthreads();

    if (t < 64) {
        float s = 0.f;
#pragma unroll 8
        for (int r = 0; r < 128; r++) s += stage[r * 66 + t];
        g_asum_part[(bIdx * 8 + tile) * 64 + t] = s;
    }
    const size_t abase = (size_t)bIdx * K_ * N_ + (size_t)tile * 128;
    for (int e = t; e < 64 * 128; e += 256) {
        int k = e >> 7, j = e & 127;
        g_aT[abase + (size_t)k * N_ + j] = __float2half(stage[j * 66 + k]);
    }
}

// ---------------- kernel 2: GEMM2 + per-batch barrier + norms + output ----------
__global__ __launch_bounds__(256, 2) void gemm2_kernel(const float* __restrict__ x,
                                                       const float* __restrict__ Cm,
                                                       float* __restrict__ out) {
    __shared__ __align__(1024) char smem[49152];
    const uint32_t S0 = smem_u32(smem);
    float* s_red  = (float*)smem;
    float* s_asum = (float*)(smem + 2048);
    float* s_inv  = (float*)(smem + 2304);
    float* s_g    = (float*)(smem + 2560);

    const int t = threadIdx.x, wid = t >> 5, l = t & 31;
    const int bIdx = (int)blockIdx.y;
    const int d0 = blockIdx.x * 128;
    const float* xb = x + (size_t)bIdx * N_ * D_ + d0;
    const __half* ath = g_aT + (size_t)bIdx * K_ * N_;

    float acc[8][4];
#pragma unroll
    for (int f = 0; f < 8; f++)
#pragma unroll
        for (int j = 0; j < 4; j++) acc[f][j] = 0.f;

    const int rT = (l & 7) + ((l >> 4) << 3);
    const int c8 = ((l >> 3) & 1) << 3;

    float4 rx[8];
    uint4  rb[2];

    auto ldg_chunk = [&](int c) {
        const int n0 = c * 64;
#pragma unroll
        for (int i = 0; i < 8; i++) {
            int e = t + i * 256, r = e >> 5, f4 = e & 31;
            rx[i] = *(const float4*)(xb + (size_t)(n0 + r) * D_ + f4 * 4);
        }
#pragma unroll
        for (int i = 0; i < 2; i++) {
            int e = t + i * 256, r = e >> 3, u = e & 7;
            rb[i] = *(const uint4*)((const char*)(ath + (size_t)r * N_ + n0) + u * 16);
        }
    };
    auto sts_chunk = [&](int buf) {
        const uint32_t XS = S0 + buf * 24576, AT = XS + 16384;
#pragma unroll
        for (int i = 0; i < 8; i++) {
            int e = t + i * 256, r = e >> 5, f4 = e & 31;
            sts64(XS + sw256((uint32_t)(r * 256 + f4 * 8)),
                  h2(rx[i].x, rx[i].y), h2(rx[i].z, rx[i].w));
        }
#pragma unroll
        for (int i = 0; i < 2; i++) {
            int e = t + i * 256, r = e >> 3, u = e & 7;
            sts128(AT + sw128((uint32_t)(r * 128 + u * 16)), rb[i]);
        }
    };

    ldg_chunk(0);
    sts_chunk(0);
    __syncthreads();

#pragma unroll 2
    for (int c = 0; c < 16; c++) {
        if (c < 15) ldg_chunk(c + 1);
        const uint32_t XS = S0 + (c & 1) * 24576, AT = XS + 16384;
#pragma unroll
        for (int ks = 0; ks < 4; ks++) {
            const int nk = ks * 16;
            uint32_t ah[4];
            ldsm_x4t(ah, XS + sw256((uint32_t)((nk + rT) * 256 + (16 * wid + c8) * 2)));
#pragma unroll
            for (int fp = 0; fp < 4; fp++) {
                uint32_t bh[4];
                ldsm_x4(bh, AT + sw128((uint32_t)((fp * 16 + rT) * 128 + (nk + c8) * 2)));
                mma16816(acc[2*fp],   ah, bh[0], bh[1]);
                mma16816(acc[2*fp+1], ah, bh[2], bh[3]);
            }
        }
        if (c < 15) {
            sts_chunk((c + 1) & 1);
            __syncthreads();
        }
    }
    __syncthreads();

    // asum[b][k]
    if (t < 64) {
        float s = 0.f;
#pragma unroll
        for (int p = 0; p < 8; p++) s += g_asum_part[(bIdx * 8 + p) * 64 + t];
        s_asum[t] = s;
    }
    __syncthreads();

    // v = acc + asum[k]*C[d,k] (regs); per-k sumsq partials
    const int q = l >> 2, qq = l & 3;
    const int dg0 = d0 + 16 * wid + q;
    float sq[8][2];
#pragma unroll
    for (int f = 0; f < 8; f++) {
        const int k0 = 8 * f + 2 * qq;
        float as0 = s_asum[k0], as1 = s_asum[k0 + 1];
        float2 c0 = *(const float2*)(Cm + (size_t)dg0 * K_ + k0);
        float2 c1 = *(const float2*)(Cm + (size_t)(dg0 + 8) * K_ + k0);
        acc[f][0] += as0 * c0.x;  acc[f][1] += as1 * c0.y;
        acc[f][2] += as0 * c1.x;  acc[f][3] += as1 * c1.y;
        sq[f][0] = acc[f][0] * acc[f][0] + acc[f][2] * acc[f][2];
        sq[f][1] = acc[f][1] * acc[f][1] + acc[f][3] * acc[f][3];
    }
#pragma unroll
    for (int f = 0; f < 8; f++)
#pragma unroll
        for (int j = 0; j < 2; j++) {
            float v = sq[f][j];
            v += __shfl_xor_sync(~0u, v, 4);
            v += __shfl_xor_sync(~0u, v, 8);
            v += __shfl_xor_sync(~0u, v, 16);
            sq[f][j] = v;
        }
    if (l < 4) {
#pragma unroll
        for (int f = 0; f < 8; f++) {
            s_red[wid * 64 + 8 * f + 2 * l]     = sq[f][0];
            s_red[wid * 64 + 8 * f + 2 * l + 1] = sq[f][1];
        }
    }
    __syncthreads();
    if (t < 64) {
        float S = 0.f;
#pragma unroll
        for (int w8 = 0; w8 < 8; w8++) S += s_red[w8 * 64 + t];
        g_S_part[(bIdx * 4 + blockIdx.x) * 64 + t] = S;
    }
    __syncthreads();

    // ---- 4-CTA per-batch barrier (co-residency via launch bounds) ----
    if (t == 0) {
        __threadfence();
        atomicAdd(&g_ctr[bIdx], 1u);
        while (atomicAdd(&g_ctr[bIdx], 0u) < 4u) __nanosleep(64);
        __threadfence();
    }
    __syncthreads();

    // ---- norms ----
    if (t < 64) {
        volatile const float* sp = g_S_part + bIdx * 4 * 64 + t;
        float s = sp[0] + sp[64] + sp[128] + sp[192];
        s_red[t] = s;
        s_inv[t] = rsqrtf(s + EPS_);
    }
    __syncthreads();
    if (t < 32) {
        float a0 = s_red[t], a1 = s_red[t + 32];
        float g = a0 / (a0 + EPS_) + a1 / (a1 + EPS_);
#pragma unroll
        for (int off = 16; off; off >>= 1) g += __shfl_xor_sync(~0u, g, off);
        if (t == 0) s_g[0] = rsqrtf(g + EPS_);
    }
    __syncthreads();
    const float gg = s_g[0];

    // ---- scale register-resident v, write out ----
    float* ob = out + (size_t)bIdx * (D_ * K_);
#pragma unroll
    for (int f = 0; f < 8; f++) {
        const int k0 = 8 * f + 2 * qq;
        float i0 = s_inv[k0] * gg, i1 = s_inv[k0 + 1] * gg;
        *(float2*)(ob + (size_t)dg0 * K_ + k0)       = make_float2(acc[f][0] * i0, acc[f][1] * i1);
        *(float2*)(ob + (size_t)(dg0 + 8) * K_ + k0) = make_float2(acc[f][2] * i0, acc[f][3] * i1);
    }

    // ---- self-cleaning counters for graph replay ----
    __syncthreads();
    if (t == 0) {
        unsigned r = atomicAdd(&g_done[bIdx], 1u);
        if (r == 3u) {
            g_ctr[bIdx]  = 0u;
            g_done[bIdx] = 0u;
            __threadfence();
        }
    }
}

// ---------------------------------------------------------------------------
extern "C" void kernel_launch(void* const* d_in, const int* in_sizes, int n_in,
                              void* d_out, int out_size) {
    const float* x  = (const float*)d_in[0];   // [B,H,W,D]
    const float* w  = (const float*)d_in[1];   // [D,K]
    const float* Cm = (const float*)d_in[2];   // [D,K]
    float* out = (float*)d_out;                // [B, D*K]

    gemm1_kernel<<<512, 256>>>(x, w);
    gemm2_kernel<<<dim3(4, B_), 256>>>(x, Cm, out);
}

// round 16
// speedup vs baseline: 1.1082x; 1.1082x over previous
#include <cuda_runtime.h>
#include <cuda_fp16.h>
#include <stdint.h>
#include <math.h>

#define B_  64
#define N_  1024
#define D_  512
#define K_  64
#define EPS_ 1e-12f

// ---------------- scratch ----------------
__device__ __half g_aT[(size_t)B_ * K_ * N_];            // a^T fp16 [b][k][n]
__device__ float g_asum_part[B_ * 8 * K_];
__device__ float g_S_part[B_ * 4 * K_];
__device__ unsigned int g_ctr[B_], g_done[B_];           // gemm2 norm barrier (self-clean)

// ---------------- helpers ----------------
__device__ __forceinline__ uint32_t smem_u32(const void* p) {
    uint32_t a;
    asm("{ .reg .u64 t; cvta.to.shared.u64 t, %1; cvt.u32.u64 %0, t; }" : "=r"(a) : "l"(p));
    return a;
}
__device__ __forceinline__ uint32_t sw128(uint32_t off) { return off ^ ((off >> 3) & 0x70); }
__device__ __forceinline__ uint32_t sw256(uint32_t off) { return off ^ (((off >> 8) & 7) << 4); }

__device__ __forceinline__ void ldsm_x4(uint32_t* r, uint32_t a) {
    asm volatile("ldmatrix.sync.aligned.m8n8.x4.shared.b16 {%0,%1,%2,%3}, [%4];"
        : "=r"(r[0]), "=r"(r[1]), "=r"(r[2]), "=r"(r[3]) : "r"(a));
}
__device__ __forceinline__ void ldsm_x4t(uint32_t* r, uint32_t a) {
    asm volatile("ldmatrix.sync.aligned.m8n8.x4.trans.shared.b16 {%0,%1,%2,%3}, [%4];"
        : "=r"(r[0]), "=r"(r[1]), "=r"(r[2]), "=r"(r[3]) : "r"(a));
}
__device__ __forceinline__ void mma16816(float* c, const uint32_t* a, uint32_t b0, uint32_t b1) {
    asm volatile("mma.sync.aligned.m16n8k16.row.col.f32.f16.f16.f32 "
        "{%0,%1,%2,%3}, {%4,%5,%6,%7}, {%8,%9}, {%0,%1,%2,%3};"
        : "+f"(c[0]), "+f"(c[1]), "+f"(c[2]), "+f"(c[3])
        : "r"(a[0]), "r"(a[1]), "r"(a[2]), "r"(a[3]), "r"(b0), "r"(b1));
}
__device__ __forceinline__ void sts64(uint32_t addr, uint32_t a, uint32_t b) {
    asm volatile("st.shared.v2.b32 [%0], {%1,%2};" :: "r"(addr), "r"(a), "r"(b) : "memory");
}
__device__ __forceinline__ void sts128(uint32_t addr, uint4 v) {
    asm volatile("st.shared.v4.b32 [%0], {%1,%2,%3,%4};"
        :: "r"(addr), "r"(v.x), "r"(v.y), "r"(v.z), "r"(v.w) : "memory");
}
__device__ __forceinline__ uint32_t h2(float a, float b) {
    __half2 h = __floats2half2_rn(a, b);
    return *(uint32_t*)&h;
}

// ---------------- kernel 1: s = x@w + softmax -> aT (w fp32 direct, trans-B) ----
// smem stage s (24KB x2): X [128n x 128B] sw128 @ s*24576 ; WD [64d x 128B] @ +16384
// post-loop overlay: stage 128x66 f32
__global__ __launch_bounds__(256) void gemm1_kernel(const float* __restrict__ x,
                                                    const float* __restrict__ w) {
    __shared__ __align__(1024) char smem[49152];
    const uint32_t S0 = smem_u32(smem);
    float* stage = (float*)smem;                   // overlay post-loop

    const int t = threadIdx.x, wid = t >> 5, l = t & 31;
    const int bIdx = blockIdx.x >> 3, tile = blockIdx.x & 7;
    const float* xb = x + ((size_t)bIdx * N_ + (size_t)tile * 128) * D_;

    float acc[8][4];
#pragma unroll
    for (int f = 0; f < 8; f++)
#pragma unroll
        for (int j = 0; j < 4; j++) acc[f][j] = 0.f;

    const int rA  = (l & 15);
    const int cA8 = (l >> 4) << 3;
    // trans-B lane mapping: row select from bit3, col select from bit4
    const int rB2 = (l & 7) + (((l >> 3) & 1) << 3);
    const int cB2 = ((l >> 4) & 1) << 3;

    float4 rx[8];
    float4 rw[4];

    auto ldg_chunk = [&](int c) {
        const int d0 = c * 64;
#pragma unroll
        for (int i = 0; i < 8; i++) {
            int e = t + i * 256, r = e >> 4, f4 = e & 15;
            rx[i] = *(const float4*)(xb + (size_t)r * D_ + d0 + f4 * 4);
        }
#pragma unroll
        for (int i = 0; i < 4; i++) {
            int e = t + i * 256, r = e >> 4, k4 = e & 15;   // 64 d-rows x 16 float4
            rw[i] = *(const float4*)(w + (size_t)(d0 + r) * K_ + k4 * 4);
        }
    };
    auto sts_chunk = [&](int buf) {
        const uint32_t XH = S0 + buf * 24576, WD = XH + 16384;
#pragma unroll
        for (int i = 0; i < 8; i++) {
            int e = t + i * 256, r = e >> 4, f4 = e & 15;
            sts64(XH + sw128((uint32_t)(r * 128 + f4 * 8)),
                  h2(rx[i].x, rx[i].y), h2(rx[i].z, rx[i].w));
        }
#pragma unroll
        for (int i = 0; i < 4; i++) {
            int e = t + i * 256, r = e >> 4, k4 = e & 15;
            sts64(WD + sw128((uint32_t)(r * 128 + k4 * 8)),
                  h2(rw[i].x, rw[i].y), h2(rw[i].z, rw[i].w));
        }
    };

    ldg_chunk(0);
    sts_chunk(0);
    __syncthreads();

#pragma unroll
    for (int c = 0; c < 8; c++) {
        if (c < 7) ldg_chunk(c + 1);
        const uint32_t XH = S0 + (c & 1) * 24576, WD = XH + 16384;
#pragma unroll
        for (int ks = 0; ks < 4; ks++) {
            const int k0 = ks * 16;           // d-offset within chunk
            uint32_t ah[4];
            ldsm_x4(ah, XH + sw128((uint32_t)((16 * wid + rA) * 128 + (k0 + cA8) * 2)));
#pragma unroll
            for (int fp = 0; fp < 4; fp++) {
                uint32_t bh[4];
                // B-frag via ldmatrix.trans from WD[d][k]
                ldsm_x4t(bh, WD + sw128((uint32_t)((k0 + rB2) * 128 + (fp * 16 + cB2) * 2)));
                mma16816(acc[2*fp],   ah, bh[0], bh[1]);
                mma16816(acc[2*fp+1], ah, bh[2], bh[3]);
            }
        }
        if (c < 7) {
            sts_chunk((c + 1) & 1);
            __syncthreads();
        }
    }
    __syncthreads();

    // softmax (rows r0 = 16*wid + l/4 and r0+8)
    const int q = l >> 2, qq = l & 3;
    const int r0 = 16 * wid + q;
    float m0 = -1e30f, m1 = -1e30f;
#pragma unroll
    for (int f = 0; f < 8; f++) {
        m0 = fmaxf(m0, fmaxf(acc[f][0], acc[f][1]));
        m1 = fmaxf(m1, fmaxf(acc[f][2], acc[f][3]));
    }
    m0 = fmaxf(m0, __shfl_xor_sync(~0u, m0, 1));
    m0 = fmaxf(m0, __shfl_xor_sync(~0u, m0, 2));
    m1 = fmaxf(m1, __shfl_xor_sync(~0u, m1, 1));
    m1 = fmaxf(m1, __shfl_xor_sync(~0u, m1, 2));
    float s0 = 0.f, s1 = 0.f;
#pragma unroll
    for (int f = 0; f < 8; f++) {
        acc[f][0] = __expf(acc[f][0] - m0);
        acc[f][1] = __expf(acc[f][1] - m0);
        acc[f][2] = __expf(acc[f][2] - m1);
        acc[f][3] = __expf(acc[f][3] - m1);
        s0 += acc[f][0] + acc[f][1];
        s1 += acc[f][2] + acc[f][3];
    }
    s0 += __shfl_xor_sync(~0u, s0, 1); s0 += __shfl_xor_sync(~0u, s0, 2);
    s1 += __shfl_xor_sync(~0u, s1, 1); s1 += __shfl_xor_sync(~0u, s1, 2);
    const float i0 = 1.0f / s0, i1 = 1.0f / s1;
#pragma unroll
    for (int f = 0; f < 8; f++) {
        *(float2*)&stage[r0 * 66 + 8 * f + 2 * qq]       = make_float2(acc[f][0] * i0, acc[f][1] * i0);
        *(float2*)&stage[(r0 + 8) * 66 + 8 * f + 2 * qq] = make_float2(acc[f][2] * i1, acc[f][3] * i1);
    }
    __syncthreads();

    if (t < 64) {
        float s = 0.f;
#pragma unroll 8
        for (int r = 0; r < 128; r++) s += stage[r * 66 + t];
        g_asum_part[(bIdx * 8 + tile) * 64 + t] = s;
    }
    const size_t abase = (size_t)bIdx * K_ * N_ + (size_t)tile * 128;
    for (int e = t; e < 64 * 128; e += 256) {
        int k = e >> 7, j = e & 127;
        g_aT[abase + (size_t)k * N_ + j] = __float2half(stage[j * 66 + k]);
    }
}

// ---------------- kernel 2: GEMM2 + per-batch barrier + norms + output ----------
// grid (4 d-tiles of 128, 64 b), 256 threads, 2 CTAs/SM -> all 256 co-resident.
__global__ __launch_bounds__(256, 2) void gemm2_kernel(const float* __restrict__ x,
                                                       const float* __restrict__ Cm,
                                                       float* __restrict__ out) {
    __shared__ __align__(1024) char smem[49152];
    const uint32_t S0 = smem_u32(smem);
    float* s_red  = (float*)smem;           // overlay post-loop: 8*64 floats
    float* s_asum = (float*)(smem + 2048);  // 64 floats
    float* s_inv  = (float*)(smem + 2304);  // 64 floats
    float* s_g    = (float*)(smem + 2560);  // 1 float

    const int t = threadIdx.x, wid = t >> 5, l = t & 31;
    const int bIdx = (int)blockIdx.y;
    const int d0 = blockIdx.x * 128;
    const float* xb = x + (size_t)bIdx * N_ * D_ + d0;
    const __half* ath = g_aT + (size_t)bIdx * K_ * N_;

    float acc[8][4];
#pragma unroll
    for (int f = 0; f < 8; f++)
#pragma unroll
        for (int j = 0; j < 4; j++) acc[f][j] = 0.f;

    const int rT = (l & 7) + ((l >> 4) << 3);
    const int c8 = ((l >> 3) & 1) << 3;

    float4 rx[8];
    uint4  rb[2];

    auto ldg_chunk = [&](int c) {
        const int n0 = c * 64;
#pragma unroll
        for (int i = 0; i < 8; i++) {
            int e = t + i * 256, r = e >> 5, f4 = e & 31;
            rx[i] = *(const float4*)(xb + (size_t)(n0 + r) * D_ + f4 * 4);
        }
#pragma unroll
        for (int i = 0; i < 2; i++) {
            int e = t + i * 256, r = e >> 3, u = e & 7;
            rb[i] = *(const uint4*)((const char*)(ath + (size_t)r * N_ + n0) + u * 16);
        }
    };
    auto sts_chunk = [&](int buf) {
        const uint32_t XS = S0 + buf * 24576, AT = XS + 16384;
#pragma unroll
        for (int i = 0; i < 8; i++) {
            int e = t + i * 256, r = e >> 5, f4 = e & 31;
            sts64(XS + sw256((uint32_t)(r * 256 + f4 * 8)),
                  h2(rx[i].x, rx[i].y), h2(rx[i].z, rx[i].w));
        }
#pragma unroll
        for (int i = 0; i < 2; i++) {
            int e = t + i * 256, r = e >> 3, u = e & 7;
            sts128(AT + sw128((uint32_t)(r * 128 + u * 16)), rb[i]);
        }
    };

    ldg_chunk(0);
    sts_chunk(0);
    __syncthreads();

#pragma unroll 1
    for (int c = 0; c < 16; c++) {
        if (c < 15) ldg_chunk(c + 1);
        const uint32_t XS = S0 + (c & 1) * 24576, AT = XS + 16384;
#pragma unroll
        for (int ks = 0; ks < 4; ks++) {
            const int nk = ks * 16;
            uint32_t ah[4];
            ldsm_x4t(ah, XS + sw256((uint32_t)((nk + rT) * 256 + (16 * wid + c8) * 2)));
#pragma unroll
            for (int fp = 0; fp < 4; fp++) {
                uint32_t bh[4];
                ldsm_x4(bh, AT + sw128((uint32_t)((fp * 16 + rT) * 128 + (nk + c8) * 2)));
                mma16816(acc[2*fp],   ah, bh[0], bh[1]);
                mma16816(acc[2*fp+1], ah, bh[2], bh[3]);
            }
        }
        if (c < 15) {
            sts_chunk((c + 1) & 1);
            __syncthreads();
        }
    }
    __syncthreads();

    // asum[b][k]
    if (t < 64) {
        float s = 0.f;
#pragma unroll
        for (int p = 0; p < 8; p++) s += g_asum_part[(bIdx * 8 + p) * 64 + t];
        s_asum[t] = s;
    }
    __syncthreads();

    // v = acc + asum[k]*C[d,k] (regs); per-k sumsq partials
    const int q = l >> 2, qq = l & 3;
    const int dg0 = d0 + 16 * wid + q;
    float sq[8][2];
#pragma unroll
    for (int f = 0; f < 8; f++) {
        const int k0 = 8 * f + 2 * qq;
        float as0 = s_asum[k0], as1 = s_asum[k0 + 1];
        float2 c0 = *(const float2*)(Cm + (size_t)dg0 * K_ + k0);
        float2 c1 = *(const float2*)(Cm + (size_t)(dg0 + 8) * K_ + k0);
        acc[f][0] += as0 * c0.x;  acc[f][1] += as1 * c0.y;
        acc[f][2] += as0 * c1.x;  acc[f][3] += as1 * c1.y;
        sq[f][0] = acc[f][0] * acc[f][0] + acc[f][2] * acc[f][2];
        sq[f][1] = acc[f][1] * acc[f][1] + acc[f][3] * acc[f][3];
    }
#pragma unroll
    for (int f = 0; f < 8; f++)
#pragma unroll
        for (int j = 0; j < 2; j++) {
            float v = sq[f][j];
            v += __shfl_xor_sync(~0u, v, 4);
            v += __shfl_xor_sync(~0u, v, 8);
            v += __shfl_xor_sync(~0u, v, 16);
            sq[f][j] = v;
        }
    if (l < 4) {
#pragma unroll
        for (int f = 0; f < 8; f++) {
            s_red[wid * 64 + 8 * f + 2 * l]     = sq[f][0];
            s_red[wid * 64 + 8 * f + 2 * l + 1] = sq[f][1];
        }
    }
    __syncthreads();
    if (t < 64) {
        float S = 0.f;
#pragma unroll
        for (int w8 = 0; w8 < 8; w8++) S += s_red[w8 * 64 + t];
        g_S_part[(bIdx * 4 + blockIdx.x) * 64 + t] = S;
    }
    __syncthreads();

    // ---- 4-CTA per-batch barrier (co-residency via launch bounds) ----
    if (t == 0) {
        __threadfence();
        atomicAdd(&g_ctr[bIdx], 1u);
        while (atomicAdd(&g_ctr[bIdx], 0u) < 4u) __nanosleep(64);
        __threadfence();
    }
    __syncthreads();

    // ---- norms ----
    if (t < 64) {
        volatile const float* sp = g_S_part + bIdx * 4 * 64 + t;
        float s = sp[0] + sp[64] + sp[128] + sp[192];
        s_red[t] = s;
        s_inv[t] = rsqrtf(s + EPS_);
    }
    __syncthreads();
    if (t < 32) {
        float a0 = s_red[t], a1 = s_red[t + 32];
        float g = a0 / (a0 + EPS_) + a1 / (a1 + EPS_);
#pragma unroll
        for (int off = 16; off; off >>= 1) g += __shfl_xor_sync(~0u, g, off);
        if (t == 0) s_g[0] = rsqrtf(g + EPS_);
    }
    __syncthreads();
    const float gg = s_g[0];

    // ---- scale register-resident v, write out ----
    float* ob = out + (size_t)bIdx * (D_ * K_);
#pragma unroll
    for (int f = 0; f < 8; f++) {
        const int k0 = 8 * f + 2 * qq;
        float i0 = s_inv[k0] * gg, i1 = s_inv[k0 + 1] * gg;
        *(float2*)(ob + (size_t)dg0 * K_ + k0)       = make_float2(acc[f][0] * i0, acc[f][1] * i1);
        *(float2*)(ob + (size_t)(dg0 + 8) * K_ + k0) = make_float2(acc[f][2] * i0, acc[f][3] * i1);
    }

    // ---- self-cleaning counters for graph replay ----
    __syncthreads();
    if (t == 0) {
        unsigned r = atomicAdd(&g_done[bIdx], 1u);
        if (r == 3u) {
            g_ctr[bIdx]  = 0u;
            g_done[bIdx] = 0u;
            __threadfence();
        }
    }
}

// ---------------------------------------------------------------------------
extern "C" void kernel_launch(void* const* d_in, const int* in_sizes, int n_in,
                              void* d_out, int out_size) {
    const float* x  = (const float*)d_in[0];   // [B,H,W,D]
    const float* w  = (const float*)d_in[1];   // [D,K]
    const float* Cm = (const float*)d_in[2];   // [D,K]
    float* out = (float*)d_out;                // [B, D*K]

    gemm1_kernel<<<512, 256>>>(x, w);
    gemm2_kernel<<<dim3(4, B_), 256>>>(x, Cm, out);
}